// round 1
// baseline (speedup 1.0000x reference)
#include <cuda_runtime.h>
#include <cuda_bf16.h>
#include <math.h>

// Problem constants
#define Bn 32
#define Tn 1024
#define INn 256
#define Hn 128
#define F2n 256
#define NG 512           // 4*H gates per direction
#define NGATES 1024      // both directions
#define Mrows (Tn*Bn)    // 32768

// ---------------- device scratch (no allocs allowed) ----------------
__device__ float g_gates[(size_t)Mrows * NGATES];   // [m][dir*512+g]
__device__ float g_out1[(size_t)Mrows * F2n];       // [t*32+b][256]
__device__ float g_out2[(size_t)Mrows * F2n];
__device__ float g_kq[Bn * F2n];
__device__ float g_qbk[Bn];
__device__ float g_vw[4 * F2n];
__device__ float g_vb[4];

// ---------------- helpers ----------------
__device__ __forceinline__ float sigmoidf_fast(float x) {
    return 1.0f / (1.0f + __expf(-x));
}
__device__ __forceinline__ float tanhf_fast(float x) {
    x = fminf(20.f, fmaxf(-20.f, x));
    float e = __expf(2.0f * x);
    return 1.0f - 2.0f / (e + 1.0f);
}

// ---------------- GEMM: gates_in = A @ W^T + (bi + bh) ----------------
// C[m][n] (m in 32768, n in 1024), K=256.
// A row m -> b=m&31, t=m>>5, addr = A + b*sB + t*sT  (unifies x layout and out1 layout)
// W row n contiguous length 256 (w_ih layer slice), bias n = bi[n]+bh[n].
#define GBK 16
__global__ __launch_bounds__(256) void gemm_gates(
    const float* __restrict__ A, size_t sB, size_t sT,
    const float* __restrict__ W,
    const float* __restrict__ bi, const float* __restrict__ bh,
    float* __restrict__ C)
{
    __shared__ float As[GBK][68];
    __shared__ float Bs[GBK][68];
    int tid = threadIdx.x;
    int tx = tid & 15, ty = tid >> 4;
    int mBase = blockIdx.y * 64;
    int nBase = blockIdx.x * 64;

    int lr = tid >> 2;          // 0..63 (row within tile)
    int lk = (tid & 3) * 4;     // 0,4,8,12

    int m = mBase + lr;
    int bb = m & 31, tt = m >> 5;
    const float* Arow = A + (size_t)bb * sB + (size_t)tt * sT;
    const float* Wrow = W + (size_t)(nBase + lr) * 256;

    float acc[4][4];
#pragma unroll
    for (int i = 0; i < 4; i++)
#pragma unroll
        for (int j2 = 0; j2 < 4; j2++) acc[i][j2] = 0.f;

    for (int kb = 0; kb < 256; kb += GBK) {
        float4 av = *(const float4*)(Arow + kb + lk);
        float4 bv = *(const float4*)(Wrow + kb + lk);
        As[lk + 0][lr] = av.x; As[lk + 1][lr] = av.y;
        As[lk + 2][lr] = av.z; As[lk + 3][lr] = av.w;
        Bs[lk + 0][lr] = bv.x; Bs[lk + 1][lr] = bv.y;
        Bs[lk + 2][lr] = bv.z; Bs[lk + 3][lr] = bv.w;
        __syncthreads();
#pragma unroll
        for (int kk = 0; kk < GBK; kk++) {
            float a0 = As[kk][ty * 4 + 0], a1 = As[kk][ty * 4 + 1];
            float a2 = As[kk][ty * 4 + 2], a3 = As[kk][ty * 4 + 3];
            float b0 = Bs[kk][tx * 4 + 0], b1 = Bs[kk][tx * 4 + 1];
            float b2 = Bs[kk][tx * 4 + 2], b3 = Bs[kk][tx * 4 + 3];
            acc[0][0] += a0 * b0; acc[0][1] += a0 * b1; acc[0][2] += a0 * b2; acc[0][3] += a0 * b3;
            acc[1][0] += a1 * b0; acc[1][1] += a1 * b1; acc[1][2] += a1 * b2; acc[1][3] += a1 * b3;
            acc[2][0] += a2 * b0; acc[2][1] += a2 * b1; acc[2][2] += a2 * b2; acc[2][3] += a2 * b3;
            acc[3][0] += a3 * b0; acc[3][1] += a3 * b1; acc[3][2] += a3 * b2; acc[3][3] += a3 * b3;
        }
        __syncthreads();
    }

    int n0 = nBase + tx * 4;
    float4 bias4;
    bias4.x = bi[n0 + 0] + bh[n0 + 0];
    bias4.y = bi[n0 + 1] + bh[n0 + 1];
    bias4.z = bi[n0 + 2] + bh[n0 + 2];
    bias4.w = bi[n0 + 3] + bh[n0 + 3];
#pragma unroll
    for (int i = 0; i < 4; i++) {
        int mi = mBase + ty * 4 + i;
        float4 v;
        v.x = acc[i][0] + bias4.x;
        v.y = acc[i][1] + bias4.y;
        v.z = acc[i][2] + bias4.z;
        v.w = acc[i][3] + bias4.w;
        *(float4*)(C + (size_t)mi * NGATES + n0) = v;
    }
}

// ---------------- LSTM recurrence ----------------
// grid = 64 blocks: dir = blockIdx.x>>5, b = blockIdx.x&31. 512 threads.
// W_hh[dir] (512x128): cols 0..63 in smem (pitch 68, conflict-free float4),
// cols 64..127 in per-thread registers.
#define WSPITCH 68
#define REC_SMEM ((512 * WSPITCH + 128 + 512) * sizeof(float))
__global__ __launch_bounds__(512, 1) void lstm_rec(
    const float* __restrict__ gates,     // [m][1024]
    const float* __restrict__ whh_layer, // [2][512][128]
    float* __restrict__ outp)            // [m][256]
{
    extern __shared__ float sm[];
    float* Ws  = sm;                     // 512*68
    float* h_s = sm + 512 * WSPITCH;     // 128
    float* gsm = h_s + 128;              // 512

    int j = threadIdx.x;
    int dir = blockIdx.x >> 5;
    int b = blockIdx.x & 31;
    const float* Wd = whh_layer + (size_t)dir * 512 * 128;

    for (int idx = j; idx < 512 * 64; idx += 512) {
        int r = idx >> 6, k = idx & 63;
        Ws[r * WSPITCH + k] = Wd[r * 128 + k];
    }
    float Wreg[64];
#pragma unroll
    for (int k = 0; k < 64; k++) Wreg[k] = Wd[j * 128 + 64 + k];

    if (j < 128) h_s[j] = 0.f;
    float c = 0.f;
    __syncthreads();

    const float* grow = gates + (size_t)b * NGATES + dir * NG + j;
    int t = dir ? (Tn - 1) : 0;
    int tstep = dir ? -1 : 1;
    float gin_next = grow[(size_t)t * (Bn * NGATES)];
    const float* wrow = Ws + j * WSPITCH;

    for (int s = 0; s < Tn; ++s) {
        float gin = gin_next;
        int tn = t + tstep;
        if (s < Tn - 1) gin_next = grow[(size_t)tn * (Bn * NGATES)];

        float acc0 = gin, acc1 = 0.f;
#pragma unroll
        for (int k = 0; k < 64; k += 4) {
            float4 h4 = *(const float4*)(h_s + k);
            float4 w4 = *(const float4*)(wrow + k);
            acc0 += w4.x * h4.x + w4.z * h4.z;
            acc1 += w4.y * h4.y + w4.w * h4.w;
        }
#pragma unroll
        for (int k = 0; k < 64; k += 4) {
            float4 h4 = *(const float4*)(h_s + 64 + k);
            acc0 += Wreg[k + 0] * h4.x + Wreg[k + 2] * h4.z;
            acc1 += Wreg[k + 1] * h4.y + Wreg[k + 3] * h4.w;
        }
        gsm[j] = acc0 + acc1;
        __syncthreads();

        if (j < 128) {
            float gi = gsm[j];
            float gf = gsm[j + 128];
            float gg = gsm[j + 256];
            float go = gsm[j + 384];
            c = sigmoidf_fast(gf) * c + sigmoidf_fast(gi) * tanhf_fast(gg);
            float h = sigmoidf_fast(go) * tanhf_fast(c);
            h_s[j] = h;
            outp[((size_t)t * Bn + b) * F2n + dir * Hn + j] = h;
        }
        __syncthreads();
        t = tn;
    }
}

// ---------------- attention prep ----------------
// blocks 0..31: per-batch q_last, kq = wk^T q, qbk = q.bk
// block 32:     vw[c] = w_fc[c] @ wv ; vb[c] = w_fc[c].bv
__global__ __launch_bounds__(256) void prep_kernel(
    const float* __restrict__ out2,
    const float* __restrict__ wq, const float* __restrict__ bq,
    const float* __restrict__ wk, const float* __restrict__ bk,
    const float* __restrict__ wv, const float* __restrict__ bv,
    const float* __restrict__ w_fc)
{
    __shared__ float osm[256];
    __shared__ float qsm[256];
    __shared__ float red[256];
    int tid = threadIdx.x;

    if (blockIdx.x < 32) {
        int b = blockIdx.x;
        osm[tid] = out2[((size_t)(Tn - 1) * Bn + b) * F2n + tid];
        __syncthreads();

        float q = bq[tid];
        const float* wrow = wq + (size_t)tid * 256;
        for (int e = 0; e < 256; e += 4) {
            float4 w4 = *(const float4*)(wrow + e);
            float4 o4 = *(const float4*)(osm + e);
            q += w4.x * o4.x + w4.y * o4.y + w4.z * o4.z + w4.w * o4.w;
        }
        qsm[tid] = q;
        __syncthreads();

        float acc = 0.f;
        for (int d = 0; d < 256; d++) acc += qsm[d] * wk[(size_t)d * 256 + tid];
        g_kq[b * 256 + tid] = acc;

        red[tid] = qsm[tid] * bk[tid];
        __syncthreads();
        for (int st = 128; st > 0; st >>= 1) {
            if (tid < st) red[tid] += red[tid + st];
            __syncthreads();
        }
        if (tid == 0) g_qbk[b] = red[0];
    } else {
#pragma unroll
        for (int cc = 0; cc < 4; cc++) {
            float acc = 0.f;
            for (int d = 0; d < 256; d++) acc += w_fc[cc * 256 + d] * wv[(size_t)d * 256 + tid];
            g_vw[cc * 256 + tid] = acc;
        }
        if (tid < 4) {
            float a = 0.f;
            for (int d = 0; d < 256; d++) a += w_fc[tid * 256 + d] * bv[d];
            g_vb[tid] = a;
        }
    }
}

// ---------------- fused attention + FC (last query only) ----------------
__global__ __launch_bounds__(256) void attn_kernel(
    const float* __restrict__ out2,
    const float* __restrict__ b_fc,
    float* __restrict__ outp)
{
    __shared__ float kqs[256];
    __shared__ float vws[4 * 256];
    __shared__ float rm[256], rd[256];
    __shared__ float ra[4][256];
    int b = blockIdx.x, tid = threadIdx.x;

    kqs[tid] = g_kq[b * 256 + tid];
#pragma unroll
    for (int cc = 0; cc < 4; cc++) vws[cc * 256 + tid] = g_vw[cc * 256 + tid];
    float qbk = g_qbk[b];
    __syncthreads();

    float m = -1e30f, den = 0.f, a0 = 0.f, a1 = 0.f, a2 = 0.f, a3 = 0.f;
    for (int t = tid; t < Tn; t += 256) {
        const float* row = out2 + ((size_t)t * Bn + b) * F2n;
        float s = 0.f, u0 = 0.f, u1 = 0.f, u2 = 0.f, u3 = 0.f;
        for (int e = 0; e < 256; e += 4) {
            float4 r = *(const float4*)(row + e);
            s  += r.x * kqs[e]   + r.y * kqs[e+1]   + r.z * kqs[e+2]   + r.w * kqs[e+3];
            u0 += r.x * vws[e]   + r.y * vws[e+1]   + r.z * vws[e+2]   + r.w * vws[e+3];
            u1 += r.x * vws[256+e] + r.y * vws[256+e+1] + r.z * vws[256+e+2] + r.w * vws[256+e+3];
            u2 += r.x * vws[512+e] + r.y * vws[512+e+1] + r.z * vws[512+e+2] + r.w * vws[512+e+3];
            u3 += r.x * vws[768+e] + r.y * vws[768+e+1] + r.z * vws[768+e+2] + r.w * vws[768+e+3];
        }
        s = (s + qbk) * 0.0625f;   // 1/sqrt(256)
        float nm = fmaxf(m, s);
        float sc = __expf(m - nm);
        float w  = __expf(s - nm);
        den = den * sc + w;
        a0 = a0 * sc + w * u0;
        a1 = a1 * sc + w * u1;
        a2 = a2 * sc + w * u2;
        a3 = a3 * sc + w * u3;
        m = nm;
    }
    rm[tid] = m; rd[tid] = den;
    ra[0][tid] = a0; ra[1][tid] = a1; ra[2][tid] = a2; ra[3][tid] = a3;
    __syncthreads();
    for (int st = 128; st > 0; st >>= 1) {
        if (tid < st) {
            float m2 = fmaxf(rm[tid], rm[tid + st]);
            float s1 = __expf(rm[tid] - m2);
            float s2 = __expf(rm[tid + st] - m2);
            rd[tid] = rd[tid] * s1 + rd[tid + st] * s2;
#pragma unroll
            for (int cc = 0; cc < 4; cc++)
                ra[cc][tid] = ra[cc][tid] * s1 + ra[cc][tid + st] * s2;
            rm[tid] = m2;
        }
        __syncthreads();
    }
    if (tid < 4) {
        outp[b * 4 + tid] = ra[tid][0] / rd[0] + g_vb[tid] + b_fc[tid];
    }
}

// ---------------- launcher ----------------
extern "C" void kernel_launch(void* const* d_in, const int* in_sizes, int n_in,
                              void* d_out, int out_size)
{
    const float* x    = (const float*)d_in[0];   // (32,1024,256)
    const float* w_ih = (const float*)d_in[1];   // (2,2,512,256)
    const float* w_hh = (const float*)d_in[2];   // (2,2,512,128)
    const float* b_ih = (const float*)d_in[3];   // (2,2,512)
    const float* b_hh = (const float*)d_in[4];   // (2,2,512)
    const float* wq   = (const float*)d_in[5];
    const float* wk   = (const float*)d_in[6];
    const float* wv   = (const float*)d_in[7];
    const float* bq   = (const float*)d_in[8];
    const float* bk   = (const float*)d_in[9];
    const float* bv   = (const float*)d_in[10];
    const float* w_fc = (const float*)d_in[11];
    const float* b_fc = (const float*)d_in[12];
    float* outp = (float*)d_out;

    float *p_gates, *p_out1, *p_out2;
    cudaGetSymbolAddress((void**)&p_gates, g_gates);
    cudaGetSymbolAddress((void**)&p_out1, g_out1);
    cudaGetSymbolAddress((void**)&p_out2, g_out2);

    cudaFuncSetAttribute(lstm_rec, cudaFuncAttributeMaxDynamicSharedMemorySize, (int)REC_SMEM);

    dim3 ggrid(16, 512);

    // layer 1: A = x, row (t,b) -> x + b*(1024*256) + t*256
    gemm_gates<<<ggrid, 256>>>(x, (size_t)Tn * INn, (size_t)INn,
                               w_ih, b_ih, b_hh, p_gates);
    lstm_rec<<<64, 512, REC_SMEM>>>(p_gates, w_hh, p_out1);

    // layer 2: A = out1, row (t,b) -> out1 + b*256 + t*(32*256)
    gemm_gates<<<ggrid, 256>>>(p_out1, (size_t)F2n, (size_t)Bn * F2n,
                               w_ih + 2 * 512 * 256, b_ih + 1024, b_hh + 1024, p_gates);
    lstm_rec<<<64, 512, REC_SMEM>>>(p_gates, w_hh + 2 * 512 * 128, p_out2);

    prep_kernel<<<33, 256>>>(p_out2, wq, bq, wk, bk, wv, bv, w_fc);
    attn_kernel<<<32, 256>>>(p_out2, b_fc, outp);
}

// round 2
// speedup vs baseline: 1.4100x; 1.4100x over previous
#include <cuda_runtime.h>
#include <cuda_bf16.h>
#include <math.h>

// Problem constants
#define Bn 32
#define Tn 1024
#define INn 256
#define Hn 128
#define F2n 256
#define NG 512           // 4*H gates per direction
#define NGATES 1024      // both directions
#define Mrows (Tn*Bn)    // 32768

typedef unsigned long long u64;

// ---------------- device scratch (no allocs allowed) ----------------
__device__ float g_gates[(size_t)Mrows * NGATES];   // [m][dir*512+g], m = t*32+b
__device__ float g_out1[(size_t)Mrows * F2n];       // [t*32+b][256]
__device__ float g_out2[(size_t)Mrows * F2n];
__device__ float g_kq[Bn * F2n];
__device__ float g_qbk[Bn];
__device__ float g_vw[4 * F2n];
__device__ float g_vb[4];

// ---------------- helpers ----------------
__device__ __forceinline__ float sigmoidf_fast(float x) {
    return 1.0f / (1.0f + __expf(-x));
}
__device__ __forceinline__ float tanhf_fast(float x) {
    x = fminf(20.f, fmaxf(-20.f, x));
    float e = __expf(2.0f * x);
    return 1.0f - 2.0f / (e + 1.0f);
}
__device__ __forceinline__ unsigned f2tf32(float f) {
    unsigned u;
    asm("cvt.rna.tf32.f32 %0, %1;" : "=r"(u) : "f"(f));
    return u;
}
__device__ __forceinline__ void ffma2(u64& acc, u64 a, u64 b) {
    asm("fma.rn.f32x2 %0, %1, %2, %0;" : "+l"(acc) : "l"(a), "l"(b));
}
__device__ __forceinline__ u64 packf2(float lo, float hi) {
    u64 r;
    asm("mov.b64 %0, {%1, %2};" : "=l"(r) : "f"(lo), "f"(hi));
    return r;
}
__device__ __forceinline__ void unpackf2(u64 v, float& lo, float& hi) {
    asm("mov.b64 {%0, %1}, %2;" : "=f"(lo), "=f"(hi) : "l"(v));
}

// ---------------- tf32 tensor-core GEMM: gates = A @ W^T + (bi+bh) ----------------
// C[m][n], m in 32768 (b = m&31, t = m>>5, A addr = A + b*sB + t*sT), n in 1024, K=256.
// CTA tile 128x128, 8 warps (2 M x 4 N), warp tile 64x32, mma m16n8k8 tf32.
__device__ __forceinline__ int sidx(int r, int k) {
    return r * 32 + ((((k >> 2) ^ (r & 7)) & 7) << 2) + (k & 3);
}

__global__ __launch_bounds__(256) void gemm_tf32(
    const float* __restrict__ A, size_t sB, size_t sT,
    const float* __restrict__ W,
    const float* __restrict__ bi, const float* __restrict__ bh,
    float* __restrict__ C)
{
    __shared__ unsigned sA[128 * 32];
    __shared__ unsigned sW[128 * 32];

    int tid = threadIdx.x;
    int wid = tid >> 5, lane = tid & 31;
    int g = lane >> 2, q = lane & 3;
    int warpM = wid & 1, warpN = wid >> 1;
    int mBase = blockIdx.y * 128;
    int nBase = blockIdx.x * 128;

    float acc[4][4][4];
#pragma unroll
    for (int mb = 0; mb < 4; mb++)
#pragma unroll
        for (int nb = 0; nb < 4; nb++)
#pragma unroll
            for (int i = 0; i < 4; i++) acc[mb][nb][i] = 0.f;

    // precompute load rows
    int lrow = tid >> 3;            // 0..31 (base row, +32*i)
    int lseg = tid & 7;             // 0..7  -> k offset seg*4

    for (int kb = 0; kb < 256; kb += 32) {
#pragma unroll
        for (int i = 0; i < 4; i++) {
            int r = lrow + 32 * i;
            int m = mBase + r;
            int bb = m & 31, tt = m >> 5;
            float4 av = *(const float4*)(A + (size_t)bb * sB + (size_t)tt * sT + kb + lseg * 4);
            float4 wv = *(const float4*)(W + (size_t)(nBase + r) * 256 + kb + lseg * 4);
            int so = r * 32 + (((lseg ^ (r & 7)) & 7) << 2);
            *(uint4*)&sA[so] = make_uint4(f2tf32(av.x), f2tf32(av.y), f2tf32(av.z), f2tf32(av.w));
            *(uint4*)&sW[so] = make_uint4(f2tf32(wv.x), f2tf32(wv.y), f2tf32(wv.z), f2tf32(wv.w));
        }
        __syncthreads();

#pragma unroll
        for (int kk = 0; kk < 4; kk++) {
            unsigned af[4][4], bf[4][2];
#pragma unroll
            for (int mb = 0; mb < 4; mb++) {
                int r = warpM * 64 + mb * 16 + g;
                af[mb][0] = sA[sidx(r,     kk * 8 + q)];
                af[mb][1] = sA[sidx(r + 8, kk * 8 + q)];
                af[mb][2] = sA[sidx(r,     kk * 8 + q + 4)];
                af[mb][3] = sA[sidx(r + 8, kk * 8 + q + 4)];
            }
#pragma unroll
            for (int nb = 0; nb < 4; nb++) {
                int n = warpN * 32 + nb * 8 + g;
                bf[nb][0] = sW[sidx(n, kk * 8 + q)];
                bf[nb][1] = sW[sidx(n, kk * 8 + q + 4)];
            }
#pragma unroll
            for (int mb = 0; mb < 4; mb++)
#pragma unroll
                for (int nb = 0; nb < 4; nb++) {
                    asm volatile(
                        "mma.sync.aligned.m16n8k8.row.col.f32.tf32.tf32.f32 "
                        "{%0,%1,%2,%3}, {%4,%5,%6,%7}, {%8,%9}, {%0,%1,%2,%3};"
                        : "+f"(acc[mb][nb][0]), "+f"(acc[mb][nb][1]),
                          "+f"(acc[mb][nb][2]), "+f"(acc[mb][nb][3])
                        : "r"(af[mb][0]), "r"(af[mb][1]), "r"(af[mb][2]), "r"(af[mb][3]),
                          "r"(bf[nb][0]), "r"(bf[nb][1]));
                }
        }
        __syncthreads();
    }

    // epilogue: add bias, write
#pragma unroll
    for (int nb = 0; nb < 4; nb++) {
        int n = nBase + warpN * 32 + nb * 8 + 2 * q;
        float bx = bi[n] + bh[n];
        float by = bi[n + 1] + bh[n + 1];
#pragma unroll
        for (int mb = 0; mb < 4; mb++) {
            int m = mBase + warpM * 64 + mb * 16 + g;
            *(float2*)(C + (size_t)m * NGATES + n) =
                make_float2(acc[mb][nb][0] + bx, acc[mb][nb][1] + by);
            *(float2*)(C + (size_t)(m + 8) * NGATES + n) =
                make_float2(acc[mb][nb][2] + bx, acc[mb][nb][3] + by);
        }
    }
}

// ---------------- LSTM recurrence (f32x2, W 96 cols in regs / 32 in smem) ----------------
// grid = 64 blocks: dir = blockIdx.x>>5, b = blockIdx.x&31. 512 threads.
#define WS2PITCH 9   // ulonglong2 per row (8 used + 1 pad)
#define REC_SMEM ((128 + 512 + 32) * sizeof(float) + 512 * WS2PITCH * sizeof(ulonglong2))
__global__ __launch_bounds__(512, 1) void lstm_rec(
    const float* __restrict__ gates,     // [m][1024]
    const float* __restrict__ whh_layer, // [2][512][128]
    float* __restrict__ outp)            // [m][256]
{
    extern __shared__ float sm[];
    float* h_s = sm;                                 // 128 floats (16B aligned)
    float* gsm = sm + 128;                           // 512 floats
    ulonglong2* Ws2 = (ulonglong2*)(sm + 128 + 512 + 32);  // 512 rows x 9

    int j = threadIdx.x;
    int dir = blockIdx.x >> 5;
    int b = blockIdx.x & 31;
    const float* Wd = whh_layer + (size_t)dir * 512 * 128;

    // fill smem W: cols 0..31 of each row, packed as ulonglong2 (4 floats)
    for (int idx = j; idx < 512 * 8; idx += 512) {
        int r = idx >> 3, q2 = idx & 7;
        Ws2[r * WS2PITCH + q2] = ((const ulonglong2*)(Wd + (size_t)r * 128))[q2];
    }
    // regs: cols 32..127 packed as 48 u64 pairs
    u64 Wreg[48];
    {
        const u64* wp = (const u64*)(Wd + (size_t)j * 128 + 32);
#pragma unroll
        for (int i = 0; i < 48; i++) Wreg[i] = wp[i];
    }

    if (j < 128) h_s[j] = 0.f;
    float c = 0.f;
    __syncthreads();

    const float* grow = gates + (size_t)b * NGATES + dir * NG + j;
    int t = dir ? (Tn - 1) : 0;
    int tstep = dir ? -1 : 1;
    float gin_next = grow[(size_t)t * (Bn * NGATES)];
    const ulonglong2* wr = Ws2 + j * WS2PITCH;
    const ulonglong2* hp = (const ulonglong2*)h_s;

    for (int s = 0; s < Tn; ++s) {
        float gin = gin_next;
        int tn = t + tstep;
        if (s < Tn - 1) gin_next = grow[(size_t)tn * (Bn * NGATES)];

        u64 acc0 = packf2(gin, 0.f);
        u64 acc1 = 0ull;
        // smem W part: cols 0..31
#pragma unroll
        for (int i = 0; i < 8; i++) {
            ulonglong2 w2 = wr[i];
            ulonglong2 h2 = hp[i];
            ffma2(acc0, w2.x, h2.x);
            ffma2(acc1, w2.y, h2.y);
        }
        // reg W part: cols 32..127
#pragma unroll
        for (int i = 0; i < 24; i++) {
            ulonglong2 h2 = hp[8 + i];
            ffma2(acc0, Wreg[2 * i], h2.x);
            ffma2(acc1, Wreg[2 * i + 1], h2.y);
        }
        float l0, h0, l1, h1;
        unpackf2(acc0, l0, h0);
        unpackf2(acc1, l1, h1);
        gsm[j] = (l0 + h0) + (l1 + h1);
        __syncthreads();

        if (j < 128) {
            float gi = gsm[j];
            float gf = gsm[j + 128];
            float gg = gsm[j + 256];
            float go = gsm[j + 384];
            c = sigmoidf_fast(gf) * c + sigmoidf_fast(gi) * tanhf_fast(gg);
            float h = sigmoidf_fast(go) * tanhf_fast(c);
            h_s[j] = h;
            outp[((size_t)t * Bn + b) * F2n + dir * Hn + j] = h;
        }
        __syncthreads();
        t = tn;
    }
}

// ---------------- attention prep ----------------
__global__ __launch_bounds__(256) void prep_kernel(
    const float* __restrict__ out2,
    const float* __restrict__ wq, const float* __restrict__ bq,
    const float* __restrict__ wk, const float* __restrict__ bk,
    const float* __restrict__ wv, const float* __restrict__ bv,
    const float* __restrict__ w_fc)
{
    __shared__ float osm[256];
    __shared__ float qsm[256];
    __shared__ float red[256];
    int tid = threadIdx.x;

    if (blockIdx.x < 32) {
        int b = blockIdx.x;
        osm[tid] = out2[((size_t)(Tn - 1) * Bn + b) * F2n + tid];
        __syncthreads();

        float q = bq[tid];
        const float* wrow = wq + (size_t)tid * 256;
        for (int e = 0; e < 256; e += 4) {
            float4 w4 = *(const float4*)(wrow + e);
            float4 o4 = *(const float4*)(osm + e);
            q += w4.x * o4.x + w4.y * o4.y + w4.z * o4.z + w4.w * o4.w;
        }
        qsm[tid] = q;
        __syncthreads();

        float acc = 0.f;
        for (int d = 0; d < 256; d++) acc += qsm[d] * wk[(size_t)d * 256 + tid];
        g_kq[b * 256 + tid] = acc;

        red[tid] = qsm[tid] * bk[tid];
        __syncthreads();
        for (int st = 128; st > 0; st >>= 1) {
            if (tid < st) red[tid] += red[tid + st];
            __syncthreads();
        }
        if (tid == 0) g_qbk[b] = red[0];
    } else {
#pragma unroll
        for (int cc = 0; cc < 4; cc++) {
            float acc = 0.f;
            for (int d = 0; d < 256; d++) acc += w_fc[cc * 256 + d] * wv[(size_t)d * 256 + tid];
            g_vw[cc * 256 + tid] = acc;
        }
        if (tid < 4) {
            float a = 0.f;
            for (int d = 0; d < 256; d++) a += w_fc[tid * 256 + d] * bv[d];
            g_vb[tid] = a;
        }
    }
}

// ---------------- fused attention + FC (last query only) ----------------
__global__ __launch_bounds__(256) void attn_kernel(
    const float* __restrict__ out2,
    const float* __restrict__ b_fc,
    float* __restrict__ outp)
{
    __shared__ float kqs[256];
    __shared__ float vws[4 * 256];
    __shared__ float rm[256], rd[256];
    __shared__ float ra[4][256];
    int b = blockIdx.x, tid = threadIdx.x;

    kqs[tid] = g_kq[b * 256 + tid];
#pragma unroll
    for (int cc = 0; cc < 4; cc++) vws[cc * 256 + tid] = g_vw[cc * 256 + tid];
    float qbk = g_qbk[b];
    __syncthreads();

    float m = -1e30f, den = 0.f, a0 = 0.f, a1 = 0.f, a2 = 0.f, a3 = 0.f;
    for (int t = tid; t < Tn; t += 256) {
        const float* row = out2 + ((size_t)t * Bn + b) * F2n;
        float s = 0.f, u0 = 0.f, u1 = 0.f, u2 = 0.f, u3 = 0.f;
        for (int e = 0; e < 256; e += 4) {
            float4 r = *(const float4*)(row + e);
            s  += r.x * kqs[e]   + r.y * kqs[e+1]   + r.z * kqs[e+2]   + r.w * kqs[e+3];
            u0 += r.x * vws[e]   + r.y * vws[e+1]   + r.z * vws[e+2]   + r.w * vws[e+3];
            u1 += r.x * vws[256+e] + r.y * vws[256+e+1] + r.z * vws[256+e+2] + r.w * vws[256+e+3];
            u2 += r.x * vws[512+e] + r.y * vws[512+e+1] + r.z * vws[512+e+2] + r.w * vws[512+e+3];
            u3 += r.x * vws[768+e] + r.y * vws[768+e+1] + r.z * vws[768+e+2] + r.w * vws[768+e+3];
        }
        s = (s + qbk) * 0.0625f;   // 1/sqrt(256)
        float nm = fmaxf(m, s);
        float sc = __expf(m - nm);
        float w  = __expf(s - nm);
        den = den * sc + w;
        a0 = a0 * sc + w * u0;
        a1 = a1 * sc + w * u1;
        a2 = a2 * sc + w * u2;
        a3 = a3 * sc + w * u3;
        m = nm;
    }
    rm[tid] = m; rd[tid] = den;
    ra[0][tid] = a0; ra[1][tid] = a1; ra[2][tid] = a2; ra[3][tid] = a3;
    __syncthreads();
    for (int st = 128; st > 0; st >>= 1) {
        if (tid < st) {
            float m2 = fmaxf(rm[tid], rm[tid + st]);
            float s1 = __expf(rm[tid] - m2);
            float s2 = __expf(rm[tid + st] - m2);
            rd[tid] = rd[tid] * s1 + rd[tid + st] * s2;
#pragma unroll
            for (int cc = 0; cc < 4; cc++)
                ra[cc][tid] = ra[cc][tid] * s1 + ra[cc][tid + st] * s2;
            rm[tid] = m2;
        }
        __syncthreads();
    }
    if (tid < 4) {
        outp[b * 4 + tid] = ra[tid][0] / rd[0] + g_vb[tid] + b_fc[tid];
    }
}

// ---------------- launcher ----------------
extern "C" void kernel_launch(void* const* d_in, const int* in_sizes, int n_in,
                              void* d_out, int out_size)
{
    const float* x    = (const float*)d_in[0];   // (32,1024,256)
    const float* w_ih = (const float*)d_in[1];   // (2,2,512,256)
    const float* w_hh = (const float*)d_in[2];   // (2,2,512,128)
    const float* b_ih = (const float*)d_in[3];   // (2,2,512)
    const float* b_hh = (const float*)d_in[4];   // (2,2,512)
    const float* wq   = (const float*)d_in[5];
    const float* wk   = (const float*)d_in[6];
    const float* wv   = (const float*)d_in[7];
    const float* bq   = (const float*)d_in[8];
    const float* bk   = (const float*)d_in[9];
    const float* bv   = (const float*)d_in[10];
    const float* w_fc = (const float*)d_in[11];
    const float* b_fc = (const float*)d_in[12];
    float* outp = (float*)d_out;

    float *p_gates, *p_out1, *p_out2;
    cudaGetSymbolAddress((void**)&p_gates, g_gates);
    cudaGetSymbolAddress((void**)&p_out1, g_out1);
    cudaGetSymbolAddress((void**)&p_out2, g_out2);

    cudaFuncSetAttribute(lstm_rec, cudaFuncAttributeMaxDynamicSharedMemorySize, (int)REC_SMEM);

    dim3 ggrid(8, 256);   // x = n-tile (fast, A reuse in L2), y = m-tile

    // layer 1: A = x, row (t,b) -> x + b*(1024*256) + t*256
    gemm_tf32<<<ggrid, 256>>>(x, (size_t)Tn * INn, (size_t)INn,
                              w_ih, b_ih, b_hh, p_gates);
    lstm_rec<<<64, 512, REC_SMEM>>>(p_gates, w_hh, p_out1);

    // layer 2: A = out1, row (t,b) -> out1 + b*256 + t*(32*256)
    gemm_tf32<<<ggrid, 256>>>(p_out1, (size_t)F2n, (size_t)Bn * F2n,
                              w_ih + 2 * 512 * 256, b_ih + 1024, b_hh + 1024, p_gates);
    lstm_rec<<<64, 512, REC_SMEM>>>(p_gates, w_hh + 2 * 512 * 128, p_out2);

    prep_kernel<<<33, 256>>>(p_out2, wq, bq, wk, bk, wv, bv, w_fc);
    attn_kernel<<<32, 256>>>(p_out2, b_fc, outp);
}

// round 3
// speedup vs baseline: 1.7067x; 1.2104x over previous
#include <cuda_runtime.h>
#include <cuda_bf16.h>
#include <math.h>

// Problem constants
#define Bn 32
#define Tn 1024
#define INn 256
#define Hn 128
#define F2n 256
#define NG 512           // 4*H gates per direction
#define NGATES 1024      // both directions
#define Mrows (Tn*Bn)    // 32768
#define PF 4             // gin prefetch depth

typedef unsigned long long u64;

// ---------------- device scratch (no allocs allowed) ----------------
__device__ float g_gates[(size_t)Mrows * NGATES];   // [m][dir*512+g], m = t*32+b
__device__ float g_out1[(size_t)Mrows * F2n];       // [t*32+b][256]
__device__ float g_out2[(size_t)Mrows * F2n];
__device__ float g_kq[Bn * F2n];
__device__ float g_qbk[Bn];
__device__ float g_vw[4 * F2n];
__device__ float g_vb[4];

// ---------------- helpers ----------------
__device__ __forceinline__ float tanh_fast(float x) {
    float r;
    asm("tanh.approx.f32 %0, %1;" : "=f"(r) : "f"(x));
    return r;
}
__device__ __forceinline__ float sig_fast(float x) {
    return 0.5f * tanh_fast(0.5f * x) + 0.5f;
}
__device__ __forceinline__ unsigned f2tf32(float f) {
    unsigned u;
    asm("cvt.rna.tf32.f32 %0, %1;" : "=r"(u) : "f"(f));
    return u;
}
__device__ __forceinline__ void ffma2(u64& acc, u64 a, u64 b) {
    asm("fma.rn.f32x2 %0, %1, %2, %0;" : "+l"(acc) : "l"(a), "l"(b));
}
__device__ __forceinline__ u64 packf2(float lo, float hi) {
    u64 r;
    asm("mov.b64 %0, {%1, %2};" : "=l"(r) : "f"(lo), "f"(hi));
    return r;
}
__device__ __forceinline__ void unpackf2(u64 v, float& lo, float& hi) {
    asm("mov.b64 {%0, %1}, %2;" : "=f"(lo), "=f"(hi) : "l"(v));
}

// ---------------- tf32 tensor-core GEMM: gates = A @ W^T + (bi+bh) ----------------
// C[m][n], m in 32768 (b = m&31, t = m>>5, A addr = A + b*sB + t*sT), n in 1024, K=256.
// CTA tile 128x128, 8 warps (2 M x 4 N), warp tile 64x32, mma m16n8k8 tf32.
// Register-staged double buffering over the 8 k-tiles.
__device__ __forceinline__ int sidx(int r, int k) {
    return r * 32 + ((((k >> 2) ^ (r & 7)) & 7) << 2) + (k & 3);
}

__global__ __launch_bounds__(256) void gemm_tf32(
    const float* __restrict__ A, size_t sB, size_t sT,
    const float* __restrict__ W,
    const float* __restrict__ bi, const float* __restrict__ bh,
    float* __restrict__ C)
{
    __shared__ unsigned sA[128 * 32];
    __shared__ unsigned sW[128 * 32];

    int tid = threadIdx.x;
    int wid = tid >> 5, lane = tid & 31;
    int g = lane >> 2, q = lane & 3;
    int warpM = wid & 1, warpN = wid >> 1;
    int mBase = blockIdx.y * 128;
    int nBase = blockIdx.x * 128;

    float acc[4][4][4];
#pragma unroll
    for (int mb = 0; mb < 4; mb++)
#pragma unroll
        for (int nb = 0; nb < 4; nb++)
#pragma unroll
            for (int i = 0; i < 4; i++) acc[mb][nb][i] = 0.f;

    int lrow = tid >> 3;            // 0..31 (base row, +32*i)
    int lseg = tid & 7;             // 0..7  -> k offset seg*4

    // precomputed row pointers
    const float* Arows[4];
    const float* Wrows[4];
#pragma unroll
    for (int i = 0; i < 4; i++) {
        int r = lrow + 32 * i;
        int m = mBase + r;
        int bb = m & 31, tt = m >> 5;
        Arows[i] = A + (size_t)bb * sB + (size_t)tt * sT + lseg * 4;
        Wrows[i] = W + (size_t)(nBase + r) * 256 + lseg * 4;
    }
    int soff[4];
#pragma unroll
    for (int i = 0; i < 4; i++) {
        int r = lrow + 32 * i;
        soff[i] = r * 32 + (((lseg ^ (r & 7)) & 7) << 2);
    }

    float4 av[4], wv[4];
#pragma unroll
    for (int i = 0; i < 4; i++) {
        av[i] = *(const float4*)(Arows[i]);
        wv[i] = *(const float4*)(Wrows[i]);
    }

    for (int kb = 0; kb < 256; kb += 32) {
#pragma unroll
        for (int i = 0; i < 4; i++) {
            *(uint4*)&sA[soff[i]] = make_uint4(f2tf32(av[i].x), f2tf32(av[i].y), f2tf32(av[i].z), f2tf32(av[i].w));
            *(uint4*)&sW[soff[i]] = make_uint4(f2tf32(wv[i].x), f2tf32(wv[i].y), f2tf32(wv[i].z), f2tf32(wv[i].w));
        }
        __syncthreads();

        if (kb + 32 < 256) {
#pragma unroll
            for (int i = 0; i < 4; i++) {
                av[i] = *(const float4*)(Arows[i] + kb + 32);
                wv[i] = *(const float4*)(Wrows[i] + kb + 32);
            }
        }

#pragma unroll
        for (int kk = 0; kk < 4; kk++) {
            unsigned af[4][4], bf[4][2];
#pragma unroll
            for (int mb = 0; mb < 4; mb++) {
                int r = warpM * 64 + mb * 16 + g;
                af[mb][0] = sA[sidx(r,     kk * 8 + q)];
                af[mb][1] = sA[sidx(r + 8, kk * 8 + q)];
                af[mb][2] = sA[sidx(r,     kk * 8 + q + 4)];
                af[mb][3] = sA[sidx(r + 8, kk * 8 + q + 4)];
            }
#pragma unroll
            for (int nb = 0; nb < 4; nb++) {
                int n = warpN * 32 + nb * 8 + g;
                bf[nb][0] = sW[sidx(n, kk * 8 + q)];
                bf[nb][1] = sW[sidx(n, kk * 8 + q + 4)];
            }
#pragma unroll
            for (int mb = 0; mb < 4; mb++)
#pragma unroll
                for (int nb = 0; nb < 4; nb++) {
                    asm volatile(
                        "mma.sync.aligned.m16n8k8.row.col.f32.tf32.tf32.f32 "
                        "{%0,%1,%2,%3}, {%4,%5,%6,%7}, {%8,%9}, {%0,%1,%2,%3};"
                        : "+f"(acc[mb][nb][0]), "+f"(acc[mb][nb][1]),
                          "+f"(acc[mb][nb][2]), "+f"(acc[mb][nb][3])
                        : "r"(af[mb][0]), "r"(af[mb][1]), "r"(af[mb][2]), "r"(af[mb][3]),
                          "r"(bf[nb][0]), "r"(bf[nb][1]));
                }
        }
        __syncthreads();
    }

    // epilogue: add bias, write
#pragma unroll
    for (int nb = 0; nb < 4; nb++) {
        int n = nBase + warpN * 32 + nb * 8 + 2 * q;
        float bx = bi[n] + bh[n];
        float by = bi[n + 1] + bh[n + 1];
#pragma unroll
        for (int mb = 0; mb < 4; mb++) {
            int m = mBase + warpM * 64 + mb * 16 + g;
            *(float2*)(C + (size_t)m * NGATES + n) =
                make_float2(acc[mb][nb][0] + bx, acc[mb][nb][1] + by);
            *(float2*)(C + (size_t)(m + 8) * NGATES + n) =
                make_float2(acc[mb][nb][2] + bx, acc[mb][nb][3] + by);
        }
    }
}

// ---------------- LSTM recurrence ----------------
// grid = 64 blocks: dir = blockIdx.x>>5, b = blockIdx.x&31. 512 threads.
// W_hh split: cols 0..31 in smem (pitch 9 u64x2, conflict-free), cols 32..127 in regs (48 u64).
// gin fed through a 4-deep cp.async ring (per-thread wait_group).
#define WS2PITCH 9
#define REC_SMEM ((128 + 512 + PF*512) * sizeof(float) + 512 * WS2PITCH * sizeof(ulonglong2))
__global__ __launch_bounds__(512, 1) void lstm_rec(
    const float* __restrict__ gates,     // [m][1024]
    const float* __restrict__ whh_layer, // [2][512][128]
    float* __restrict__ outp)            // [m][256]
{
    extern __shared__ float sm[];
    float* h_s = sm;                                   // 128
    float* gsm = sm + 128;                             // 512
    float* gring = sm + 640;                           // PF*512
    ulonglong2* Ws2 = (ulonglong2*)(sm + 640 + PF * 512);

    int j = threadIdx.x;
    int dir = blockIdx.x >> 5;
    int b = blockIdx.x & 31;
    const float* Wd = whh_layer + (size_t)dir * 512 * 128;

    // smem W: cols 0..31
    for (int idx = j; idx < 512 * 8; idx += 512) {
        int r = idx >> 3, q2 = idx & 7;
        Ws2[r * WS2PITCH + q2] = ((const ulonglong2*)(Wd + (size_t)r * 128))[q2];
    }
    // regs: cols 32..127 as 48 u64 pairs
    u64 Wreg[48];
    {
        const u64* wp = (const u64*)(Wd + (size_t)j * 128 + 32);
#pragma unroll
        for (int i = 0; i < 48; i++) Wreg[i] = wp[i];
    }

    if (j < 128) h_s[j] = 0.f;
    float c = 0.f;
    __syncthreads();

    int tstep = dir ? -1 : 1;
    int t0 = dir ? (Tn - 1) : 0;

    // cp.async ring setup
    unsigned ring = (unsigned)__cvta_generic_to_shared(gring) + ((unsigned)j << 2);
    const float* gld = gates + (size_t)b * NGATES + dir * NG + j + (size_t)t0 * (Bn * NGATES);
    long gstep = (long)tstep * (Bn * NGATES);
#pragma unroll
    for (int d = 0; d < PF; d++) {
        asm volatile("cp.async.ca.shared.global [%0], [%1], 4;\n"
                     "cp.async.commit_group;"
                     :: "r"(ring + ((unsigned)d << 11)), "l"(gld) : "memory");
        gld += gstep;
    }

    float* op = outp + ((size_t)t0 * Bn + b) * F2n + dir * Hn + j;
    long ostep = (long)tstep * Bn * F2n;

    const ulonglong2* wr = Ws2 + j * WS2PITCH;
    const ulonglong2* hp = (const ulonglong2*)h_s;

    for (int s = 0; s < Tn; ++s) {
        asm volatile("cp.async.wait_group 3;" ::: "memory");
        float gin = gring[((s & 3) << 9) | j];

        // refill consumed slot with t = s + PF
        if (s < Tn - PF) {
            asm volatile("cp.async.ca.shared.global [%0], [%1], 4;"
                         :: "r"(ring + (((unsigned)s & 3u) << 11)), "l"(gld) : "memory");
            gld += gstep;
        }
        asm volatile("cp.async.commit_group;" ::: "memory");

        u64 acc0 = packf2(gin, 0.f);
        u64 acc1 = 0ull;
#pragma unroll
        for (int i = 0; i < 8; i++) {
            ulonglong2 w2 = wr[i];
            ulonglong2 h2 = hp[i];
            ffma2(acc0, w2.x, h2.x);
            ffma2(acc1, w2.y, h2.y);
        }
#pragma unroll
        for (int i = 0; i < 24; i++) {
            ulonglong2 h2 = hp[8 + i];
            ffma2(acc0, Wreg[2 * i], h2.x);
            ffma2(acc1, Wreg[2 * i + 1], h2.y);
        }
        float l0, h0, l1, h1;
        unpackf2(acc0, l0, h0);
        unpackf2(acc1, l1, h1);
        gsm[j] = (l0 + h0) + (l1 + h1);
        __syncthreads();

        if (j < 128) {
            float gi = gsm[j];
            float gf = gsm[j + 128];
            float gg = gsm[j + 256];
            float go = gsm[j + 384];
            c = sig_fast(gf) * c + sig_fast(gi) * tanh_fast(gg);
            float h = sig_fast(go) * tanh_fast(c);
            h_s[j] = h;
            *op = h;
        }
        __syncthreads();
        op += ostep;
    }
}

// ---------------- attention prep ----------------
__global__ __launch_bounds__(256) void prep_kernel(
    const float* __restrict__ out2,
    const float* __restrict__ wq, const float* __restrict__ bq,
    const float* __restrict__ wk, const float* __restrict__ bk,
    const float* __restrict__ wv, const float* __restrict__ bv,
    const float* __restrict__ w_fc)
{
    __shared__ float osm[256];
    __shared__ float qsm[256];
    __shared__ float red[256];
    int tid = threadIdx.x;

    if (blockIdx.x < 32) {
        int b = blockIdx.x;
        osm[tid] = out2[((size_t)(Tn - 1) * Bn + b) * F2n + tid];
        __syncthreads();

        float q = bq[tid];
        const float* wrow = wq + (size_t)tid * 256;
        for (int e = 0; e < 256; e += 4) {
            float4 w4 = *(const float4*)(wrow + e);
            float4 o4 = *(const float4*)(osm + e);
            q += w4.x * o4.x + w4.y * o4.y + w4.z * o4.z + w4.w * o4.w;
        }
        qsm[tid] = q;
        __syncthreads();

        float acc = 0.f;
        for (int d = 0; d < 256; d++) acc += qsm[d] * wk[(size_t)d * 256 + tid];
        g_kq[b * 256 + tid] = acc;

        red[tid] = qsm[tid] * bk[tid];
        __syncthreads();
        for (int st = 128; st > 0; st >>= 1) {
            if (tid < st) red[tid] += red[tid + st];
            __syncthreads();
        }
        if (tid == 0) g_qbk[b] = red[0];
    } else {
#pragma unroll
        for (int cc = 0; cc < 4; cc++) {
            float acc = 0.f;
            for (int d = 0; d < 256; d++) acc += w_fc[cc * 256 + d] * wv[(size_t)d * 256 + tid];
            g_vw[cc * 256 + tid] = acc;
        }
        if (tid < 4) {
            float a = 0.f;
            for (int d = 0; d < 256; d++) a += w_fc[tid * 256 + d] * bv[d];
            g_vb[tid] = a;
        }
    }
}

// ---------------- fused attention + FC (last query only) ----------------
__global__ __launch_bounds__(256) void attn_kernel(
    const float* __restrict__ out2,
    const float* __restrict__ b_fc,
    float* __restrict__ outp)
{
    __shared__ float kqs[256];
    __shared__ float vws[4 * 256];
    __shared__ float rm[256], rd[256];
    __shared__ float ra[4][256];
    int b = blockIdx.x, tid = threadIdx.x;

    kqs[tid] = g_kq[b * 256 + tid];
#pragma unroll
    for (int cc = 0; cc < 4; cc++) vws[cc * 256 + tid] = g_vw[cc * 256 + tid];
    float qbk = g_qbk[b];
    __syncthreads();

    float m = -1e30f, den = 0.f, a0 = 0.f, a1 = 0.f, a2 = 0.f, a3 = 0.f;
    for (int t = tid; t < Tn; t += 256) {
        const float* row = out2 + ((size_t)t * Bn + b) * F2n;
        float s = 0.f, u0 = 0.f, u1 = 0.f, u2 = 0.f, u3 = 0.f;
        for (int e = 0; e < 256; e += 4) {
            float4 r = *(const float4*)(row + e);
            s  += r.x * kqs[e]   + r.y * kqs[e+1]   + r.z * kqs[e+2]   + r.w * kqs[e+3];
            u0 += r.x * vws[e]   + r.y * vws[e+1]   + r.z * vws[e+2]   + r.w * vws[e+3];
            u1 += r.x * vws[256+e] + r.y * vws[256+e+1] + r.z * vws[256+e+2] + r.w * vws[256+e+3];
            u2 += r.x * vws[512+e] + r.y * vws[512+e+1] + r.z * vws[512+e+2] + r.w * vws[512+e+3];
            u3 += r.x * vws[768+e] + r.y * vws[768+e+1] + r.z * vws[768+e+2] + r.w * vws[768+e+3];
        }
        s = (s + qbk) * 0.0625f;   // 1/sqrt(256)
        float nm = fmaxf(m, s);
        float sc = __expf(m - nm);
        float w  = __expf(s - nm);
        den = den * sc + w;
        a0 = a0 * sc + w * u0;
        a1 = a1 * sc + w * u1;
        a2 = a2 * sc + w * u2;
        a3 = a3 * sc + w * u3;
        m = nm;
    }
    rm[tid] = m; rd[tid] = den;
    ra[0][tid] = a0; ra[1][tid] = a1; ra[2][tid] = a2; ra[3][tid] = a3;
    __syncthreads();
    for (int st = 128; st > 0; st >>= 1) {
        if (tid < st) {
            float m2 = fmaxf(rm[tid], rm[tid + st]);
            float s1 = __expf(rm[tid] - m2);
            float s2 = __expf(rm[tid + st] - m2);
            rd[tid] = rd[tid] * s1 + rd[tid + st] * s2;
#pragma unroll
            for (int cc = 0; cc < 4; cc++)
                ra[cc][tid] = ra[cc][tid] * s1 + ra[cc][tid + st] * s2;
            rm[tid] = m2;
        }
        __syncthreads();
    }
    if (tid < 4) {
        outp[b * 4 + tid] = ra[tid][0] / rd[0] + g_vb[tid] + b_fc[tid];
    }
}

// ---------------- launcher ----------------
extern "C" void kernel_launch(void* const* d_in, const int* in_sizes, int n_in,
                              void* d_out, int out_size)
{
    const float* x    = (const float*)d_in[0];   // (32,1024,256)
    const float* w_ih = (const float*)d_in[1];   // (2,2,512,256)
    const float* w_hh = (const float*)d_in[2];   // (2,2,512,128)
    const float* b_ih = (const float*)d_in[3];   // (2,2,512)
    const float* b_hh = (const float*)d_in[4];   // (2,2,512)
    const float* wq   = (const float*)d_in[5];
    const float* wk   = (const float*)d_in[6];
    const float* wv   = (const float*)d_in[7];
    const float* bq   = (const float*)d_in[8];
    const float* bk   = (const float*)d_in[9];
    const float* bv   = (const float*)d_in[10];
    const float* w_fc = (const float*)d_in[11];
    const float* b_fc = (const float*)d_in[12];
    float* outp = (float*)d_out;

    float *p_gates, *p_out1, *p_out2;
    cudaGetSymbolAddress((void**)&p_gates, g_gates);
    cudaGetSymbolAddress((void**)&p_out1, g_out1);
    cudaGetSymbolAddress((void**)&p_out2, g_out2);

    cudaFuncSetAttribute(lstm_rec, cudaFuncAttributeMaxDynamicSharedMemorySize, (int)REC_SMEM);

    dim3 ggrid(8, 256);   // x = n-tile, y = m-tile

    // layer 1: A = x, row (t,b) -> x + b*(1024*256) + t*256
    gemm_tf32<<<ggrid, 256>>>(x, (size_t)Tn * INn, (size_t)INn,
                              w_ih, b_ih, b_hh, p_gates);
    lstm_rec<<<64, 512, REC_SMEM>>>(p_gates, w_hh, p_out1);

    // layer 2: A = out1, row (t,b) -> out1 + b*256 + t*(32*256)
    gemm_tf32<<<ggrid, 256>>>(p_out1, (size_t)F2n, (size_t)Bn * F2n,
                              w_ih + 2 * 512 * 256, b_ih + 1024, b_hh + 1024, p_gates);
    lstm_rec<<<64, 512, REC_SMEM>>>(p_gates, w_hh + 2 * 512 * 128, p_out2);

    prep_kernel<<<33, 256>>>(p_out2, wq, bq, wk, bk, wv, bv, w_fc);
    attn_kernel<<<32, 256>>>(p_out2, b_fc, outp);
}